// round 15
// baseline (speedup 1.0000x reference)
#include <cuda_runtime.h>
#include <cuda_bf16.h>
#include <cuda_fp16.h>
#include <cstdint>

// Problem constants: B=8, T=12, N=512, D_MODEL=128, K_HEADS=8, D_HEAD=16.
#define DMODEL   128
#define KHEADS   8
#define DHEAD    16
#define NSEQ     512
#define MMAX     49152

// ---------------- generic-ISA tensor helpers (compute_103-safe) ------------
__device__ __forceinline__ uint32_t smem_to_u32(const void* p) {
    uint32_t a;
    asm("{ .reg .u64 t; cvta.to.shared.u64 t, %1; cvt.u32.u64 %0, t; }"
        : "=r"(a) : "l"(p));
    return a;
}
__device__ __forceinline__ void ldsm_x4(uint32_t* r, uint32_t addr) {
    asm volatile("ldmatrix.sync.aligned.m8n8.x4.shared.b16 {%0,%1,%2,%3}, [%4];"
                 : "=r"(r[0]), "=r"(r[1]), "=r"(r[2]), "=r"(r[3]) : "r"(addr));
}
__device__ __forceinline__ void ldsm_x4t(uint32_t* r, uint32_t addr) {
    asm volatile("ldmatrix.sync.aligned.m8n8.x4.trans.shared.b16 {%0,%1,%2,%3}, [%4];"
                 : "=r"(r[0]), "=r"(r[1]), "=r"(r[2]), "=r"(r[3]) : "r"(addr));
}
__device__ __forceinline__ void ldsm_x2t(uint32_t* r, uint32_t addr) {
    asm volatile("ldmatrix.sync.aligned.m8n8.x2.trans.shared.b16 {%0,%1}, [%2];"
                 : "=r"(r[0]), "=r"(r[1]) : "r"(addr));
}
__device__ __forceinline__ void mma_bf16(float* d, const uint32_t* a,
                                         uint32_t b0, uint32_t b1) {
    asm volatile("mma.sync.aligned.m16n8k16.row.col.f32.bf16.bf16.f32 "
                 "{%0,%1,%2,%3}, {%4,%5,%6,%7}, {%8,%9}, {%0,%1,%2,%3};"
                 : "+f"(d[0]), "+f"(d[1]), "+f"(d[2]), "+f"(d[3])
                 : "r"(a[0]), "r"(a[1]), "r"(a[2]), "r"(a[3]), "r"(b0), "r"(b1));
}
// zero-C variant: writes d without prior init (saves the 4 MOVs)
__device__ __forceinline__ void mma_bf16_z(float* d, const uint32_t* a,
                                           uint32_t b0, uint32_t b1) {
    asm volatile("mma.sync.aligned.m16n8k16.row.col.f32.bf16.bf16.f32 "
                 "{%0,%1,%2,%3}, {%4,%5,%6,%7}, {%8,%9}, {%10,%10,%10,%10};"
                 : "=f"(d[0]), "=f"(d[1]), "=f"(d[2]), "=f"(d[3])
                 : "r"(a[0]), "r"(a[1]), "r"(a[2]), "r"(a[3]), "r"(b0), "r"(b1),
                   "f"(0.0f));
}
__device__ __forceinline__ void mma_f16(float* d, const uint32_t* a,
                                        uint32_t b0, uint32_t b1) {
    asm volatile("mma.sync.aligned.m16n8k16.row.col.f32.f16.f16.f32 "
                 "{%0,%1,%2,%3}, {%4,%5,%6,%7}, {%8,%9}, {%0,%1,%2,%3};"
                 : "+f"(d[0]), "+f"(d[1]), "+f"(d[2]), "+f"(d[3])
                 : "r"(a[0]), "r"(a[1]), "r"(a[2]), "r"(a[3]), "r"(b0), "r"(b1));
}
__device__ __forceinline__ void mma_f16_z(float* d, const uint32_t* a,
                                          uint32_t b0, uint32_t b1) {
    asm volatile("mma.sync.aligned.m16n8k16.row.col.f32.f16.f16.f32 "
                 "{%0,%1,%2,%3}, {%4,%5,%6,%7}, {%8,%9}, {%10,%10,%10,%10};"
                 : "=f"(d[0]), "=f"(d[1]), "=f"(d[2]), "=f"(d[3])
                 : "r"(a[0]), "r"(a[1]), "r"(a[2]), "r"(a[3]), "r"(b0), "r"(b1),
                   "f"(0.0f));
}
#define CP_ASYNC16(dst_u32, src_ptr) \
    asm volatile("cp.async.ca.shared.global [%0], [%1], 16;" \
                 :: "r"(dst_u32), "l"(src_ptr))
#define CP_COMMIT() asm volatile("cp.async.commit_group;" ::: "memory")
#define CP_WAIT(n)  asm volatile("cp.async.wait_group %0;" :: "n"(n) : "memory")

// cheap split: packed cvt + shift-unpack (bf16->f32 is a 16-bit shift)
__device__ __forceinline__ void split2(float x, float y, uint32_t& hi, uint32_t& lo) {
    uint32_t h;
    asm("cvt.rn.bf16x2.f32 %0, %1, %2;" : "=r"(h) : "f"(y), "f"(x));
    const float hx = __uint_as_float(h << 16);
    const float hy = __uint_as_float(h & 0xffff0000u);
    uint32_t l;
    asm("cvt.rn.bf16x2.f32 %0, %1, %2;" : "=r"(l) : "f"(y - hy), "f"(x - hx));
    hi = h; lo = l;
}
__device__ __forceinline__ uint32_t packh2(float x, float y) {
    const half2 h = __floats2half2_rn(x, y);
    return *(const uint32_t*)&h;
}

// ---------------- scratch --------------------------------------------------
__device__ float g_q[(size_t)MMAX * DMODEL];
__device__ float g_k[(size_t)MMAX * DMODEL];
__device__ float g_v[(size_t)MMAX * DMODEL];
__device__ __nv_bfloat16 g_ahi[(size_t)MMAX * 384];
__device__ __nv_bfloat16 g_alo[(size_t)MMAX * 384];
__device__ __nv_bfloat16 g_ohi[(size_t)MMAX * DMODEL];
__device__ __nv_bfloat16 g_olo[(size_t)MMAX * DMODEL];
#define W_TOTAL (3 * 49152 + 16384)
__device__ __nv_bfloat16 g_whi[W_TOTAL];
__device__ __nv_bfloat16 g_wlo[W_TOTAL];
#define WOFF_O 147456

// ===========================================================================
// Pre-split kernels
// ===========================================================================
__global__ void presplit_x_kernel(const float* __restrict__ X,
                                  const float* __restrict__ STE, int M,
                                  __nv_bfloat16* __restrict__ ahi,
                                  __nv_bfloat16* __restrict__ alo)
{
    const int total = M * 96;
    for (int i = blockIdx.x * blockDim.x + threadIdx.x; i < total;
         i += gridDim.x * blockDim.x) {
        const int m = i / 96, c = (i % 96) * 4;
        const float4 x = (c < 128)
            ? *(const float4*)&X[(size_t)m * 128 + c]
            : *(const float4*)&STE[(size_t)m * 256 + (c - 128)];
        uint32_t h0, l0, h1, l1;
        split2(x.x, x.y, h0, l0);
        split2(x.z, x.w, h1, l1);
        *(uint2*)&ahi[(size_t)m * 384 + c] = make_uint2(h0, h1);
        *(uint2*)&alo[(size_t)m * 384 + c] = make_uint2(l0, l1);
    }
}

__global__ void presplit_w_kernel(const float* __restrict__ Wq,
                                  const float* __restrict__ Wk,
                                  const float* __restrict__ Wv,
                                  const float* __restrict__ Wo,
                                  __nv_bfloat16* __restrict__ whi,
                                  __nv_bfloat16* __restrict__ wlo)
{
    const int i = blockIdx.x * blockDim.x + threadIdx.x;
    if (i >= W_TOTAL / 4) return;
    const float* src; int off;
    if      (i < 12288) { src = Wq; off = 0; }
    else if (i < 24576) { src = Wk; off = 12288; }
    else if (i < 36864) { src = Wv; off = 24576; }
    else                { src = Wo; off = 36864; }
    const int j = (i - off) * 4;
    const float4 x = *(const float4*)&src[j];
    uint32_t h0, l0, h1, l1;
    split2(x.x, x.y, h0, l0);
    split2(x.z, x.w, h1, l1);
    *(uint2*)&whi[off * 4 + j] = make_uint2(h0, h1);
    *(uint2*)&wlo[off * 4 + j] = make_uint2(l0, l1);
}

// ===========================================================================
// Pipelined mma.sync GEMM core (unchanged, proven)
// ===========================================================================
#define GK      32
#define GA_LD   40
#define GB_LD   136
#define GA_BUF  (128 * GA_LD * 2)
#define GB_BUF  (GK * GB_LD * 2)
#define GSM_A   0
#define GSM_B   (4 * GA_BUF)
#define GEMM_SMEM (GSM_B + 4 * GB_BUF)   // 75776

__device__ __forceinline__ void gemm_core(
    const __nv_bfloat16* __restrict__ Ahi,
    const __nv_bfloat16* __restrict__ Alo,
    int lda, int K, int rowBase,
    const __nv_bfloat16* __restrict__ Whi,
    const __nv_bfloat16* __restrict__ Wlo,
    const float* __restrict__ bias, float* __restrict__ C,
    uint32_t sb)
{
    const int tid  = threadIdx.x;
    const int warp = tid >> 5;
    const int lane = tid & 31;
    const int wm   = warp & 3;
    const int wn   = warp >> 2;

    float acc[2][8][4];
#pragma unroll
    for (int mt = 0; mt < 2; mt++)
#pragma unroll
        for (int nt = 0; nt < 8; nt++)
#pragma unroll
            for (int e = 0; e < 4; e++) acc[mt][nt][e] = 0.0f;

    const int nChunks = K / GK;

    auto load_chunk = [&](int c, int buf) {
        const int k0 = c * GK;
        {
            const int r = tid >> 1;
#pragma unroll
            for (int hl = 0; hl < 2; hl++) {
                const __nv_bfloat16* gsrc =
                    (hl ? Alo : Ahi) + (size_t)(rowBase + r) * lda + k0;
                const uint32_t dbase =
                    sb + GSM_A + (buf * 2 + hl) * GA_BUF + r * (GA_LD * 2);
#pragma unroll
                for (int s2 = 0; s2 < 2; s2++) {
                    const int s = (tid & 1) * 2 + s2;
                    CP_ASYNC16(dbase + s * 16, gsrc + s * 8);
                }
            }
        }
        {
            const int kk = tid >> 3;
#pragma unroll
            for (int hl = 0; hl < 2; hl++) {
                const __nv_bfloat16* gsrc =
                    (hl ? Wlo : Whi) + (size_t)(k0 + kk) * 128;
                const uint32_t dbase =
                    sb + GSM_B + (buf * 2 + hl) * GB_BUF + kk * (GB_LD * 2);
#pragma unroll
                for (int s2 = 0; s2 < 2; s2++) {
                    const int s = (tid & 7) * 2 + s2;
                    CP_ASYNC16(dbase + s * 16, gsrc + s * 8);
                }
            }
        }
        CP_COMMIT();
    };

    load_chunk(0, 0);

    for (int c = 0; c < nChunks; c++) {
        if (c + 1 < nChunks) { load_chunk(c + 1, (c + 1) & 1); CP_WAIT(1); }
        else                 { CP_WAIT(0); }
        __syncthreads();

        const int buf = c & 1;
        const uint32_t abase_h = sb + GSM_A + (buf * 2 + 0) * GA_BUF;
        const uint32_t abase_l = sb + GSM_A + (buf * 2 + 1) * GA_BUF;
        const uint32_t bbase_h = sb + GSM_B + (buf * 2 + 0) * GB_BUF;
        const uint32_t bbase_l = sb + GSM_B + (buf * 2 + 1) * GB_BUF;

#pragma unroll
        for (int ks = 0; ks < 2; ks++) {
            uint32_t ah[2][4], al[2][4];
            const int arow = lane & 15;
            const int acol = ks * 16 + (lane >> 4) * 8;
#pragma unroll
            for (int mt = 0; mt < 2; mt++) {
                const uint32_t aoff =
                    ((wm * 32 + mt * 16 + arow) * GA_LD + acol) * 2;
                ldsm_x4(ah[mt], abase_h + aoff);
                ldsm_x4(al[mt], abase_l + aoff);
            }
            const int brow = ks * 16 + (lane & 15);
#pragma unroll
            for (int np = 0; np < 4; np++) {
                const uint32_t boff =
                    (brow * GB_LD + wn * 64 + np * 16 + (lane >> 4) * 8) * 2;
                uint32_t bh[4], bl[4];
                ldsm_x4t(bh, bbase_h + boff);
                ldsm_x4t(bl, bbase_l + boff);
#pragma unroll
                for (int sub = 0; sub < 2; sub++) {
                    const int nt = np * 2 + sub;
#pragma unroll
                    for (int mt = 0; mt < 2; mt++) {
                        mma_bf16(acc[mt][nt], ah[mt], bh[2 * sub], bh[2 * sub + 1]);
                        mma_bf16(acc[mt][nt], ah[mt], bl[2 * sub], bl[2 * sub + 1]);
                        mma_bf16(acc[mt][nt], al[mt], bh[2 * sub], bh[2 * sub + 1]);
                    }
                }
            }
        }
        __syncthreads();
    }

#pragma unroll
    for (int mt = 0; mt < 2; mt++) {
        const int r0 = rowBase + wm * 32 + mt * 16 + (lane >> 2);
#pragma unroll
        for (int nt = 0; nt < 8; nt++) {
            const int cc = wn * 64 + nt * 8 + (lane & 3) * 2;
            const float b0 = bias[cc], b1 = bias[cc + 1];
            float2 lo, hi;
            lo.x = fmaxf(acc[mt][nt][0] + b0, 0.0f);
            lo.y = fmaxf(acc[mt][nt][1] + b1, 0.0f);
            hi.x = fmaxf(acc[mt][nt][2] + b0, 0.0f);
            hi.y = fmaxf(acc[mt][nt][3] + b1, 0.0f);
            *(float2*)&C[(size_t)r0 * 128 + cc]       = lo;
            *(float2*)&C[(size_t)(r0 + 8) * 128 + cc] = hi;
        }
    }
}

// QKV grid-fused (round-14 winner)
__global__ __launch_bounds__(256, 2)
void qkv_grid_kernel(const __nv_bfloat16* __restrict__ Ahi,
                     const __nv_bfloat16* __restrict__ Alo,
                     const __nv_bfloat16* __restrict__ whi,
                     const __nv_bfloat16* __restrict__ wlo,
                     const float* __restrict__ bq,
                     const float* __restrict__ bk,
                     const float* __restrict__ bv,
                     float* __restrict__ qo, float* __restrict__ ko,
                     float* __restrict__ vo)
{
    extern __shared__ __align__(16) char smc[];
    const uint32_t sb = smem_to_u32(smc);
    const int wsel = blockIdx.x;
    const __nv_bfloat16* Whi = whi + (size_t)wsel * 49152;
    const __nv_bfloat16* Wlo = wlo + (size_t)wsel * 49152;
    const float* bias = (wsel == 0) ? bq : (wsel == 1) ? bk : bv;
    float* dst        = (wsel == 0) ? qo : (wsel == 1) ? ko : vo;
    gemm_core(Ahi, Alo, 384, 384, blockIdx.y * 128, Whi, Wlo, bias, dst, sb);
}

__global__ __launch_bounds__(256, 2)
void gemm_ps_kernel(const __nv_bfloat16* __restrict__ Ahi,
                    const __nv_bfloat16* __restrict__ Alo,
                    int lda, int K,
                    const __nv_bfloat16* __restrict__ Whi,
                    const __nv_bfloat16* __restrict__ Wlo,
                    const float* __restrict__ bias, float* __restrict__ C)
{
    extern __shared__ __align__(16) char smc[];
    const uint32_t sb = smem_to_u32(smc);
    gemm_core(Ahi, Alo, lda, K, blockIdx.x * 128, Whi, Wlo, bias, C, sb);
}

// ===========================================================================
// Attention v7: global-max-first softmax (no per-warp rescale, no fp32 sum
// chain); row-sums computed by the tensor core via a ones-column in V;
// zero-C mma variants kill accumulator init. S stays 3-term bf16.
// ===========================================================================
#define KLD 520
#define VLD 24
#define KT_BYTES (16 * KLD * 2)
#define VS_BYTES (NSEQ * VLD * 2)
#define OFF_KT_HI 0
#define OFF_KT_LO (OFF_KT_HI + KT_BYTES)
#define OFF_VS    (OFF_KT_LO + KT_BYTES)
#define OFF_OBUF  (OFF_VS + VS_BYTES)
#define OFF_MAX   (OFF_OBUF + 4 * 32 * 16 * 4)    // float[4][32]
#define OFF_WGT   (OFF_MAX + 4 * 32 * 4)          // float[4][32]
#define ATTN_SMEM (OFF_WGT + 4 * 32 * 4)          // 67072 bytes

#define QSCALE 0.3606737602f    /* 0.25 * log2(e) */

__global__ __launch_bounds__(256, 2)
void attn_tc_kernel(const float* __restrict__ q, const float* __restrict__ k,
                    const float* __restrict__ v,
                    __nv_bfloat16* __restrict__ ohi,
                    __nv_bfloat16* __restrict__ olo)
{
    extern __shared__ __align__(16) char smc[];
    const uint32_t sb = smem_to_u32(smc);
    __nv_bfloat16* kt_hi = (__nv_bfloat16*)(smc + OFF_KT_HI);
    __nv_bfloat16* kt_lo = (__nv_bfloat16*)(smc + OFF_KT_LO);
    __half*        vs    = (__half*)(smc + OFF_VS);
    float*  obuf   = (float*)(smc + OFF_OBUF);
    float*  maxbuf = (float*)(smc + OFF_MAX);
    float*  wgtbuf = (float*)(smc + OFF_WGT);

    const int bt   = blockIdx.x;
    const int h    = blockIdx.y;
    const int tid  = threadIdx.x;
    const int warp = tid >> 5;
    const int lane = tid & 31;
    const int wm   = warp & 1;
    const int wn   = warp >> 1;
    const size_t base = (size_t)bt * NSEQ * DMODEL + h * DHEAD;

    // ---- stage K^T (bf16 hi/lo), V (fp16) with ones-column at col 16
    for (int idx = tid; idx < NSEQ * 8; idx += 256) {
        const int m = idx >> 3, dp = (idx & 7) * 2;
        const float2 kv = *(const float2*)&k[base + (size_t)m * DMODEL + dp];
        uint32_t kh, kl;
        split2(kv.x, kv.y, kh, kl);
        kt_hi[dp * KLD + m] = __ushort_as_bfloat16((unsigned short)(kh & 0xffffu));
        kt_hi[(dp + 1) * KLD + m] = __ushort_as_bfloat16((unsigned short)(kh >> 16));
        kt_lo[dp * KLD + m] = __ushort_as_bfloat16((unsigned short)(kl & 0xffffu));
        kt_lo[(dp + 1) * KLD + m] = __ushort_as_bfloat16((unsigned short)(kl >> 16));

        const float2 vv = *(const float2*)&v[base + (size_t)m * DMODEL + dp];
        *(uint32_t*)&vs[m * VLD + dp] = packh2(vv.x, vv.y);
    }
    for (int m = tid; m < NSEQ; m += 256) {
        *(uint32_t*)&vs[m * VLD + 16] = packh2(1.0f, 0.0f);  // ones col + zero
        *(uint32_t*)&vs[m * VLD + 18] = 0u;                  // keep cols 18-23 clean
        *(uint32_t*)&vs[m * VLD + 20] = 0u;
        *(uint32_t*)&vs[m * VLD + 22] = 0u;
    }
    __syncthreads();

    const int lq = lane >> 2;
    const int lc = lane & 3;

    for (int t0 = 0; t0 < NSEQ; t0 += 32) {
        // ---- Q fragment, scaled by 0.25*log2e, split bf16
        uint32_t qh[4], ql[4];
        {
            const float* qrow = q + base + (size_t)(t0 + wm * 16 + lq) * DMODEL;
            const float2 x0 = *(const float2*)&qrow[2 * lc];
            const float2 x1 = *(const float2*)&qrow[8 + 2 * lc];
            const float2 y0 = *(const float2*)&qrow[8 * DMODEL + 2 * lc];
            const float2 y1 = *(const float2*)&qrow[8 * DMODEL + 8 + 2 * lc];
            split2(QSCALE * x0.x, QSCALE * x0.y, qh[0], ql[0]);
            split2(QSCALE * y0.x, QSCALE * y0.y, qh[1], ql[1]);
            split2(QSCALE * x1.x, QSCALE * x1.y, qh[2], ql[2]);
            split2(QSCALE * y1.x, QSCALE * y1.y, qh[3], ql[3]);
        }

        // ---- S = Q K^T (3-term), zero-C first term (no init pass)
        float sacc[16][4];
#pragma unroll
        for (int np = 0; np < 8; np++) {
            const int key0 = wn * 128 + np * 16;
            const uint32_t kaddr =
                sb + OFF_KT_HI + ((lane & 15) * KLD + key0 + (lane >> 4) * 8) * 2;
            uint32_t bh[4], bl[4];
            ldsm_x4t(bh, kaddr);
            ldsm_x4t(bl, kaddr + KT_BYTES);
#pragma unroll
            for (int sub = 0; sub < 2; sub++) {
                const int nt = np * 2 + sub;
                mma_bf16_z(sacc[nt], qh, bh[2 * sub], bh[2 * sub + 1]);
                mma_bf16(sacc[nt], qh, bl[2 * sub], bl[2 * sub + 1]);
                mma_bf16(sacc[nt], ql, bh[2 * sub], bh[2 * sub + 1]);
            }
        }

        // ---- local max, publish, then GLOBAL max before exponentiating
        float m0 = -1e30f, m1 = -1e30f;
#pragma unroll
        for (int nt = 0; nt < 16; nt++) {
            m0 = fmaxf(m0, fmaxf(sacc[nt][0], sacc[nt][1]));
            m1 = fmaxf(m1, fmaxf(sacc[nt][2], sacc[nt][3]));
        }
        m0 = fmaxf(m0, __shfl_xor_sync(0xffffffffu, m0, 1));
        m0 = fmaxf(m0, __shfl_xor_sync(0xffffffffu, m0, 2));
        m1 = fmaxf(m1, __shfl_xor_sync(0xffffffffu, m1, 1));
        m1 = fmaxf(m1, __shfl_xor_sync(0xffffffffu, m1, 2));
        if (lc == 0) {
            maxbuf[wn * 32 + wm * 16 + lq]     = m0;
            maxbuf[wn * 32 + wm * 16 + lq + 8] = m1;
        }
        __syncthreads();

        float M0 = maxbuf[wm * 16 + lq],      M1 = maxbuf[wm * 16 + lq + 8];
#pragma unroll
        for (int w = 1; w < 4; w++) {
            M0 = fmaxf(M0, maxbuf[w * 32 + wm * 16 + lq]);
            M1 = fmaxf(M1, maxbuf[w * 32 + wm * 16 + lq + 8]);
        }

        // ---- P = exp2(s - M), packed straight to fp16 (no rescale, no sum)
        uint32_t ph_all[32];
#pragma unroll
        for (int nt = 0; nt < 16; nt++) {
            const float e0 = exp2f(sacc[nt][0] - M0);
            const float e1 = exp2f(sacc[nt][1] - M0);
            const float e2 = exp2f(sacc[nt][2] - M1);
            const float e3 = exp2f(sacc[nt][3] - M1);
            ph_all[nt * 2]     = packh2(e0, e1);
            ph_all[nt * 2 + 1] = packh2(e2, e3);
        }

        // ---- O_num = P V ; row weights via ones-column mma
        float oac[2][4], ow[4];
#pragma unroll
        for (int t = 0; t < 8; t++) {
            const uint32_t* ph = &ph_all[4 * t];
            const int key0 = wn * 128 + t * 16;
            const uint32_t vaddr =
                sb + OFF_VS + ((key0 + (lane & 15)) * VLD + (lane >> 4) * 8) * 2;
            uint32_t vh[4], vo1[2];
            ldsm_x4t(vh, vaddr);
            ldsm_x2t(vo1, sb + OFF_VS + ((key0 + (lane & 15)) * VLD + 16) * 2);
            if (t == 0) {
                mma_f16_z(oac[0], ph, vh[0], vh[1]);
                mma_f16_z(oac[1], ph, vh[2], vh[3]);
                mma_f16_z(ow,     ph, vo1[0], vo1[1]);
            } else {
                mma_f16(oac[0], ph, vh[0], vh[1]);
                mma_f16(oac[1], ph, vh[2], vh[3]);
                mma_f16(ow,     ph, vo1[0], vo1[1]);
            }
        }

        // ---- publish per-warp partials (numerator + weight), reduce, store
        {
            float* ob = obuf + wn * 512;
            const int r0 = wm * 16 + lq;
#pragma unroll
            for (int sub = 0; sub < 2; sub++) {
                const int d0 = sub * 8 + 2 * lc;
                *(float2*)&ob[r0 * 16 + d0] =
                    make_float2(oac[sub][0], oac[sub][1]);
                *(float2*)&ob[(r0 + 8) * 16 + d0] =
                    make_float2(oac[sub][2], oac[sub][3]);
            }
            if (lc == 0) {
                wgtbuf[wn * 32 + r0]     = ow[0];
                wgtbuf[wn * 32 + r0 + 8] = ow[2];
            }
        }
        __syncthreads();
        if (tid < 128) {
            const int q4  = tid * 4;
            const int row = q4 >> 4;
            const int d0  = q4 & 15;
            const float4 a = *(const float4*)&obuf[row * 16 + d0];
            const float4 b = *(const float4*)&obuf[512 + row * 16 + d0];
            const float4 c = *(const float4*)&obuf[1024 + row * 16 + d0];
            const float4 d = *(const float4*)&obuf[1536 + row * 16 + d0];
            const float wsum = wgtbuf[row] + wgtbuf[32 + row]
                             + wgtbuf[64 + row] + wgtbuf[96 + row];
            const float inv = 1.0f / wsum;
            float4 r;
            r.x = (a.x + b.x + c.x + d.x) * inv;
            r.y = (a.y + b.y + c.y + d.y) * inv;
            r.z = (a.z + b.z + c.z + d.z) * inv;
            r.w = (a.w + b.w + c.w + d.w) * inv;
            uint32_t h0, l0, h1, l1;
            split2(r.x, r.y, h0, l0);
            split2(r.z, r.w, h1, l1);
            const size_t go = base + (size_t)(t0 + row) * DMODEL + d0;
            *(uint2*)&ohi[go] = make_uint2(h0, h1);
            *(uint2*)&olo[go] = make_uint2(l0, l1);
        }
        __syncthreads();
    }
}

// ===========================================================================
extern "C" void kernel_launch(void* const* d_in, const int* in_sizes, int n_in,
                              void* d_out, int out_size)
{
    const float* X   = (const float*)d_in[0];
    const float* STE = (const float*)d_in[1];
    const float* Wq  = (const float*)d_in[2];
    const float* bq  = (const float*)d_in[3];
    const float* Wk  = (const float*)d_in[4];
    const float* bk  = (const float*)d_in[5];
    const float* Wv  = (const float*)d_in[6];
    const float* bv  = (const float*)d_in[7];
    const float* Wo  = (const float*)d_in[8];
    const float* bo  = (const float*)d_in[9];
    float* out = (float*)d_out;

    const int M  = in_sizes[0] / DMODEL;   // 49152
    const int BT = M / NSEQ;               // 96

    float *q, *k, *v;
    __nv_bfloat16 *ahi, *alo, *whi, *wlo, *ohi, *olo;
    cudaGetSymbolAddress((void**)&q,   g_q);
    cudaGetSymbolAddress((void**)&k,   g_k);
    cudaGetSymbolAddress((void**)&v,   g_v);
    cudaGetSymbolAddress((void**)&ahi, g_ahi);
    cudaGetSymbolAddress((void**)&alo, g_alo);
    cudaGetSymbolAddress((void**)&whi, g_whi);
    cudaGetSymbolAddress((void**)&wlo, g_wlo);
    cudaGetSymbolAddress((void**)&ohi, g_ohi);
    cudaGetSymbolAddress((void**)&olo, g_olo);

    presplit_x_kernel<<<4608, 256>>>(X, STE, M, ahi, alo);
    presplit_w_kernel<<<160, 256>>>(Wq, Wk, Wv, Wo, whi, wlo);

    cudaFuncSetAttribute(qkv_grid_kernel, cudaFuncAttributeMaxDynamicSharedMemorySize,
                         GEMM_SMEM);
    qkv_grid_kernel<<<dim3(3, M / 128), 256, GEMM_SMEM>>>(
        ahi, alo, whi, wlo, bq, bk, bv, q, k, v);

    cudaFuncSetAttribute(attn_tc_kernel, cudaFuncAttributeMaxDynamicSharedMemorySize,
                         ATTN_SMEM);
    attn_tc_kernel<<<dim3(BT, KHEADS), 256, ATTN_SMEM>>>(q, k, v, ohi, olo);

    cudaFuncSetAttribute(gemm_ps_kernel, cudaFuncAttributeMaxDynamicSharedMemorySize,
                         GEMM_SMEM);
    gemm_ps_kernel<<<M / 128, 256, GEMM_SMEM>>>(ohi, olo, 128, 128,
                                                whi + WOFF_O, wlo + WOFF_O, bo, out);
}

// round 16
// speedup vs baseline: 1.4482x; 1.4482x over previous
#include <cuda_runtime.h>
#include <cuda_bf16.h>
#include <cuda_fp16.h>
#include <cstdint>

// Problem constants: B=8, T=12, N=512, D_MODEL=128, K_HEADS=8, D_HEAD=16.
#define DMODEL   128
#define KHEADS   8
#define DHEAD    16
#define NSEQ     512
#define MMAX     49152

// ---------------- generic-ISA tensor helpers (compute_103-safe) ------------
__device__ __forceinline__ uint32_t smem_to_u32(const void* p) {
    uint32_t a;
    asm("{ .reg .u64 t; cvta.to.shared.u64 t, %1; cvt.u32.u64 %0, t; }"
        : "=r"(a) : "l"(p));
    return a;
}
__device__ __forceinline__ void ldsm_x4(uint32_t* r, uint32_t addr) {
    asm volatile("ldmatrix.sync.aligned.m8n8.x4.shared.b16 {%0,%1,%2,%3}, [%4];"
                 : "=r"(r[0]), "=r"(r[1]), "=r"(r[2]), "=r"(r[3]) : "r"(addr));
}
__device__ __forceinline__ void ldsm_x4t(uint32_t* r, uint32_t addr) {
    asm volatile("ldmatrix.sync.aligned.m8n8.x4.trans.shared.b16 {%0,%1,%2,%3}, [%4];"
                 : "=r"(r[0]), "=r"(r[1]), "=r"(r[2]), "=r"(r[3]) : "r"(addr));
}
__device__ __forceinline__ void ldsm_x2t(uint32_t* r, uint32_t addr) {
    asm volatile("ldmatrix.sync.aligned.m8n8.x2.trans.shared.b16 {%0,%1}, [%2];"
                 : "=r"(r[0]), "=r"(r[1]) : "r"(addr));
}
__device__ __forceinline__ void mma_bf16(float* d, const uint32_t* a,
                                         uint32_t b0, uint32_t b1) {
    asm volatile("mma.sync.aligned.m16n8k16.row.col.f32.bf16.bf16.f32 "
                 "{%0,%1,%2,%3}, {%4,%5,%6,%7}, {%8,%9}, {%0,%1,%2,%3};"
                 : "+f"(d[0]), "+f"(d[1]), "+f"(d[2]), "+f"(d[3])
                 : "r"(a[0]), "r"(a[1]), "r"(a[2]), "r"(a[3]), "r"(b0), "r"(b1));
}
__device__ __forceinline__ void mma_bf16_z(float* d, const uint32_t* a,
                                           uint32_t b0, uint32_t b1) {
    asm volatile("mma.sync.aligned.m16n8k16.row.col.f32.bf16.bf16.f32 "
                 "{%0,%1,%2,%3}, {%4,%5,%6,%7}, {%8,%9}, {%10,%10,%10,%10};"
                 : "=f"(d[0]), "=f"(d[1]), "=f"(d[2]), "=f"(d[3])
                 : "r"(a[0]), "r"(a[1]), "r"(a[2]), "r"(a[3]), "r"(b0), "r"(b1),
                   "f"(0.0f));
}
__device__ __forceinline__ void mma_f16(float* d, const uint32_t* a,
                                        uint32_t b0, uint32_t b1) {
    asm volatile("mma.sync.aligned.m16n8k16.row.col.f32.f16.f16.f32 "
                 "{%0,%1,%2,%3}, {%4,%5,%6,%7}, {%8,%9}, {%0,%1,%2,%3};"
                 : "+f"(d[0]), "+f"(d[1]), "+f"(d[2]), "+f"(d[3])
                 : "r"(a[0]), "r"(a[1]), "r"(a[2]), "r"(a[3]), "r"(b0), "r"(b1));
}
__device__ __forceinline__ void mma_f16_z(float* d, const uint32_t* a,
                                          uint32_t b0, uint32_t b1) {
    asm volatile("mma.sync.aligned.m16n8k16.row.col.f32.f16.f16.f32 "
                 "{%0,%1,%2,%3}, {%4,%5,%6,%7}, {%8,%9}, {%10,%10,%10,%10};"
                 : "=f"(d[0]), "=f"(d[1]), "=f"(d[2]), "=f"(d[3])
                 : "r"(a[0]), "r"(a[1]), "r"(a[2]), "r"(a[3]), "r"(b0), "r"(b1),
                   "f"(0.0f));
}
#define CP_ASYNC16(dst_u32, src_ptr) \
    asm volatile("cp.async.ca.shared.global [%0], [%1], 16;" \
                 :: "r"(dst_u32), "l"(src_ptr))
#define CP_COMMIT() asm volatile("cp.async.commit_group;" ::: "memory")
#define CP_WAIT(n)  asm volatile("cp.async.wait_group %0;" :: "n"(n) : "memory")

__device__ __forceinline__ void split2(float x, float y, uint32_t& hi, uint32_t& lo) {
    uint32_t h;
    asm("cvt.rn.bf16x2.f32 %0, %1, %2;" : "=r"(h) : "f"(y), "f"(x));
    const float hx = __uint_as_float(h << 16);
    const float hy = __uint_as_float(h & 0xffff0000u);
    uint32_t l;
    asm("cvt.rn.bf16x2.f32 %0, %1, %2;" : "=r"(l) : "f"(y - hy), "f"(x - hx));
    hi = h; lo = l;
}
__device__ __forceinline__ uint32_t packh2(float x, float y) {
    const half2 h = __floats2half2_rn(x, y);
    return *(const uint32_t*)&h;
}

#define QSCALE 0.3606737602f    /* 0.25 * log2(e) */

// ---------------- scratch --------------------------------------------------
__device__ __nv_bfloat16 g_qhi[(size_t)MMAX * DMODEL];
__device__ __nv_bfloat16 g_qlo[(size_t)MMAX * DMODEL];
__device__ __nv_bfloat16 g_khi[(size_t)MMAX * DMODEL];
__device__ __nv_bfloat16 g_klo[(size_t)MMAX * DMODEL];
__device__ __half        g_vh [(size_t)MMAX * DMODEL];
__device__ __nv_bfloat16 g_ahi[(size_t)MMAX * 384];
__device__ __nv_bfloat16 g_alo[(size_t)MMAX * 384];
__device__ __nv_bfloat16 g_ohi[(size_t)MMAX * DMODEL];
__device__ __nv_bfloat16 g_olo[(size_t)MMAX * DMODEL];
#define W_TOTAL (3 * 49152 + 16384)
__device__ __nv_bfloat16 g_whi[W_TOTAL];
__device__ __nv_bfloat16 g_wlo[W_TOTAL];
#define WOFF_O 147456

// ===========================================================================
// Pre-split kernels
// ===========================================================================
__global__ void presplit_x_kernel(const float* __restrict__ X,
                                  const float* __restrict__ STE, int M,
                                  __nv_bfloat16* __restrict__ ahi,
                                  __nv_bfloat16* __restrict__ alo)
{
    const int total = M * 96;
    for (int i = blockIdx.x * blockDim.x + threadIdx.x; i < total;
         i += gridDim.x * blockDim.x) {
        const int m = i / 96, c = (i % 96) * 4;
        const float4 x = (c < 128)
            ? *(const float4*)&X[(size_t)m * 128 + c]
            : *(const float4*)&STE[(size_t)m * 256 + (c - 128)];
        uint32_t h0, l0, h1, l1;
        split2(x.x, x.y, h0, l0);
        split2(x.z, x.w, h1, l1);
        *(uint2*)&ahi[(size_t)m * 384 + c] = make_uint2(h0, h1);
        *(uint2*)&alo[(size_t)m * 384 + c] = make_uint2(l0, l1);
    }
}

__global__ void presplit_w_kernel(const float* __restrict__ Wq,
                                  const float* __restrict__ Wk,
                                  const float* __restrict__ Wv,
                                  const float* __restrict__ Wo,
                                  __nv_bfloat16* __restrict__ whi,
                                  __nv_bfloat16* __restrict__ wlo)
{
    const int i = blockIdx.x * blockDim.x + threadIdx.x;
    if (i >= W_TOTAL / 4) return;
    const float* src; int off;
    if      (i < 12288) { src = Wq; off = 0; }
    else if (i < 24576) { src = Wk; off = 12288; }
    else if (i < 36864) { src = Wv; off = 24576; }
    else                { src = Wo; off = 36864; }
    const int j = (i - off) * 4;
    const float4 x = *(const float4*)&src[j];
    uint32_t h0, l0, h1, l1;
    split2(x.x, x.y, h0, l0);
    split2(x.z, x.w, h1, l1);
    *(uint2*)&whi[off * 4 + j] = make_uint2(h0, h1);
    *(uint2*)&wlo[off * 4 + j] = make_uint2(l0, l1);
}

// ===========================================================================
// Pipelined mma.sync GEMM core, templated epilogue:
//   MODE 0: fp32 C (out-projection)       MODE 1: q -> scaled split-bf16
//   MODE 2: k -> split-bf16               MODE 3: v -> fp16
// ===========================================================================
#define GK      32
#define GA_LD   40
#define GB_LD   136
#define GA_BUF  (128 * GA_LD * 2)
#define GB_BUF  (GK * GB_LD * 2)
#define GSM_A   0
#define GSM_B   (4 * GA_BUF)
#define GEMM_SMEM (GSM_B + 4 * GB_BUF)   // 75776

template<int MODE>
__device__ __forceinline__ void gemm_core_t(
    const __nv_bfloat16* __restrict__ Ahi,
    const __nv_bfloat16* __restrict__ Alo,
    int lda, int K, int rowBase,
    const __nv_bfloat16* __restrict__ Whi,
    const __nv_bfloat16* __restrict__ Wlo,
    const float* __restrict__ bias,
    void* __restrict__ D0, void* __restrict__ D1,
    uint32_t sb)
{
    const int tid  = threadIdx.x;
    const int warp = tid >> 5;
    const int lane = tid & 31;
    const int wm   = warp & 3;
    const int wn   = warp >> 2;

    float acc[2][8][4];
#pragma unroll
    for (int mt = 0; mt < 2; mt++)
#pragma unroll
        for (int nt = 0; nt < 8; nt++)
#pragma unroll
            for (int e = 0; e < 4; e++) acc[mt][nt][e] = 0.0f;

    const int nChunks = K / GK;

    auto load_chunk = [&](int c, int buf) {
        const int k0 = c * GK;
        {
            const int r = tid >> 1;
#pragma unroll
            for (int hl = 0; hl < 2; hl++) {
                const __nv_bfloat16* gsrc =
                    (hl ? Alo : Ahi) + (size_t)(rowBase + r) * lda + k0;
                const uint32_t dbase =
                    sb + GSM_A + (buf * 2 + hl) * GA_BUF + r * (GA_LD * 2);
#pragma unroll
                for (int s2 = 0; s2 < 2; s2++) {
                    const int s = (tid & 1) * 2 + s2;
                    CP_ASYNC16(dbase + s * 16, gsrc + s * 8);
                }
            }
        }
        {
            const int kk = tid >> 3;
#pragma unroll
            for (int hl = 0; hl < 2; hl++) {
                const __nv_bfloat16* gsrc =
                    (hl ? Wlo : Whi) + (size_t)(k0 + kk) * 128;
                const uint32_t dbase =
                    sb + GSM_B + (buf * 2 + hl) * GB_BUF + kk * (GB_LD * 2);
#pragma unroll
                for (int s2 = 0; s2 < 2; s2++) {
                    const int s = (tid & 7) * 2 + s2;
                    CP_ASYNC16(dbase + s * 16, gsrc + s * 8);
                }
            }
        }
        CP_COMMIT();
    };

    load_chunk(0, 0);

    for (int c = 0; c < nChunks; c++) {
        if (c + 1 < nChunks) { load_chunk(c + 1, (c + 1) & 1); CP_WAIT(1); }
        else                 { CP_WAIT(0); }
        __syncthreads();

        const int buf = c & 1;
        const uint32_t abase_h = sb + GSM_A + (buf * 2 + 0) * GA_BUF;
        const uint32_t abase_l = sb + GSM_A + (buf * 2 + 1) * GA_BUF;
        const uint32_t bbase_h = sb + GSM_B + (buf * 2 + 0) * GB_BUF;
        const uint32_t bbase_l = sb + GSM_B + (buf * 2 + 1) * GB_BUF;

#pragma unroll
        for (int ks = 0; ks < 2; ks++) {
            uint32_t ah[2][4], al[2][4];
            const int arow = lane & 15;
            const int acol = ks * 16 + (lane >> 4) * 8;
#pragma unroll
            for (int mt = 0; mt < 2; mt++) {
                const uint32_t aoff =
                    ((wm * 32 + mt * 16 + arow) * GA_LD + acol) * 2;
                ldsm_x4(ah[mt], abase_h + aoff);
                ldsm_x4(al[mt], abase_l + aoff);
            }
            const int brow = ks * 16 + (lane & 15);
#pragma unroll
            for (int np = 0; np < 4; np++) {
                const uint32_t boff =
                    (brow * GB_LD + wn * 64 + np * 16 + (lane >> 4) * 8) * 2;
                uint32_t bh[4], bl[4];
                ldsm_x4t(bh, bbase_h + boff);
                ldsm_x4t(bl, bbase_l + boff);
#pragma unroll
                for (int sub = 0; sub < 2; sub++) {
                    const int nt = np * 2 + sub;
#pragma unroll
                    for (int mt = 0; mt < 2; mt++) {
                        mma_bf16(acc[mt][nt], ah[mt], bh[2 * sub], bh[2 * sub + 1]);
                        mma_bf16(acc[mt][nt], ah[mt], bl[2 * sub], bl[2 * sub + 1]);
                        mma_bf16(acc[mt][nt], al[mt], bh[2 * sub], bh[2 * sub + 1]);
                    }
                }
            }
        }
        __syncthreads();
    }

    // ---- epilogue: bias + relu, then MODE-specific conversion/store
#pragma unroll
    for (int mt = 0; mt < 2; mt++) {
        const int r0 = rowBase + wm * 32 + mt * 16 + (lane >> 2);
#pragma unroll
        for (int nt = 0; nt < 8; nt++) {
            const int cc = wn * 64 + nt * 8 + (lane & 3) * 2;
            const float b0 = bias[cc], b1 = bias[cc + 1];
            const float v00 = fmaxf(acc[mt][nt][0] + b0, 0.0f);
            const float v01 = fmaxf(acc[mt][nt][1] + b1, 0.0f);
            const float v10 = fmaxf(acc[mt][nt][2] + b0, 0.0f);
            const float v11 = fmaxf(acc[mt][nt][3] + b1, 0.0f);
            const size_t o0 = (size_t)r0 * 128 + cc;
            const size_t o1 = (size_t)(r0 + 8) * 128 + cc;
            if (MODE == 0) {
                *(float2*)&((float*)D0)[o0] = make_float2(v00, v01);
                *(float2*)&((float*)D0)[o1] = make_float2(v10, v11);
            } else if (MODE == 1 || MODE == 2) {
                const float s = (MODE == 1) ? QSCALE : 1.0f;
                uint32_t h0, l0, h1, l1;
                split2(s * v00, s * v01, h0, l0);
                split2(s * v10, s * v11, h1, l1);
                *(uint32_t*)&((__nv_bfloat16*)D0)[o0] = h0;
                *(uint32_t*)&((__nv_bfloat16*)D1)[o0] = l0;
                *(uint32_t*)&((__nv_bfloat16*)D0)[o1] = h1;
                *(uint32_t*)&((__nv_bfloat16*)D1)[o1] = l1;
            } else {
                *(uint32_t*)&((__half*)D0)[o0] = packh2(v00, v01);
                *(uint32_t*)&((__half*)D0)[o1] = packh2(v10, v11);
            }
        }
    }
}

// QKV grid-fused, per-wsel epilogue format (q scaled split, k split, v fp16)
__global__ __launch_bounds__(256, 2)
void qkv_grid_kernel(const __nv_bfloat16* __restrict__ Ahi,
                     const __nv_bfloat16* __restrict__ Alo,
                     const __nv_bfloat16* __restrict__ whi,
                     const __nv_bfloat16* __restrict__ wlo,
                     const float* __restrict__ bq,
                     const float* __restrict__ bk,
                     const float* __restrict__ bv,
                     __nv_bfloat16* __restrict__ qhi,
                     __nv_bfloat16* __restrict__ qlo,
                     __nv_bfloat16* __restrict__ khi,
                     __nv_bfloat16* __restrict__ klo,
                     __half* __restrict__ vh)
{
    extern __shared__ __align__(16) char smc[];
    const uint32_t sb = smem_to_u32(smc);
    const int wsel = blockIdx.x;
    const int rowBase = blockIdx.y * 128;
    const __nv_bfloat16* Whi = whi + (size_t)wsel * 49152;
    const __nv_bfloat16* Wlo = wlo + (size_t)wsel * 49152;
    if (wsel == 0)
        gemm_core_t<1>(Ahi, Alo, 384, 384, rowBase, Whi, Wlo, bq, qhi, qlo, sb);
    else if (wsel == 1)
        gemm_core_t<2>(Ahi, Alo, 384, 384, rowBase, Whi, Wlo, bk, khi, klo, sb);
    else
        gemm_core_t<3>(Ahi, Alo, 384, 384, rowBase, Whi, Wlo, bv, vh, nullptr, sb);
}

// Output projection (fp32 out)
__global__ __launch_bounds__(256, 2)
void gemm_ps_kernel(const __nv_bfloat16* __restrict__ Ahi,
                    const __nv_bfloat16* __restrict__ Alo,
                    int lda, int K,
                    const __nv_bfloat16* __restrict__ Whi,
                    const __nv_bfloat16* __restrict__ Wlo,
                    const float* __restrict__ bias, float* __restrict__ C)
{
    extern __shared__ __align__(16) char smc[];
    const uint32_t sb = smem_to_u32(smc);
    gemm_core_t<0>(Ahi, Alo, lda, K, blockIdx.x * 128, Whi, Wlo, bias, C,
                   nullptr, sb);
}

// ===========================================================================
// Attention v8 = v7 with ALL conversions pre-done: Q/K/V arrive in final
// formats; staging and Q-fragment loads are pure copies (no split2/packh2).
// ===========================================================================
#define KLD 520
#define VLD 24
#define KT_BYTES (16 * KLD * 2)
#define VS_BYTES (NSEQ * VLD * 2)
#define OFF_KT_HI 0
#define OFF_KT_LO (OFF_KT_HI + KT_BYTES)
#define OFF_VS    (OFF_KT_LO + KT_BYTES)
#define OFF_OBUF  (OFF_VS + VS_BYTES)
#define OFF_MAX   (OFF_OBUF + 4 * 32 * 16 * 4)
#define OFF_WGT   (OFF_MAX + 4 * 32 * 4)
#define ATTN_SMEM (OFF_WGT + 4 * 32 * 4)          // 67072 bytes

__global__ __launch_bounds__(256, 2)
void attn_tc_kernel(const __nv_bfloat16* __restrict__ qhi,
                    const __nv_bfloat16* __restrict__ qlo,
                    const __nv_bfloat16* __restrict__ khi,
                    const __nv_bfloat16* __restrict__ klo,
                    const __half* __restrict__ vh,
                    __nv_bfloat16* __restrict__ ohi,
                    __nv_bfloat16* __restrict__ olo)
{
    extern __shared__ __align__(16) char smc[];
    const uint32_t sb = smem_to_u32(smc);
    __nv_bfloat16* kt_hi = (__nv_bfloat16*)(smc + OFF_KT_HI);
    __nv_bfloat16* kt_lo = (__nv_bfloat16*)(smc + OFF_KT_LO);
    __half*        vs    = (__half*)(smc + OFF_VS);
    float*  obuf   = (float*)(smc + OFF_OBUF);
    float*  maxbuf = (float*)(smc + OFF_MAX);
    float*  wgtbuf = (float*)(smc + OFF_WGT);

    const int bt   = blockIdx.x;
    const int h    = blockIdx.y;
    const int tid  = threadIdx.x;
    const int warp = tid >> 5;
    const int lane = tid & 31;
    const int wm   = warp & 1;
    const int wn   = warp >> 1;
    const size_t base = (size_t)bt * NSEQ * DMODEL + h * DHEAD;

    // ---- stage K^T (copy+transpose, no math) and V (straight u32 copies)
    for (int idx = tid; idx < NSEQ * 8; idx += 256) {
        const int m = idx >> 3, dp = (idx & 7) * 2;
        const uint32_t h2 = *(const uint32_t*)&khi[base + (size_t)m * DMODEL + dp];
        const uint32_t l2 = *(const uint32_t*)&klo[base + (size_t)m * DMODEL + dp];
        kt_hi[dp * KLD + m]       = __ushort_as_bfloat16((unsigned short)(h2 & 0xffffu));
        kt_hi[(dp + 1) * KLD + m] = __ushort_as_bfloat16((unsigned short)(h2 >> 16));
        kt_lo[dp * KLD + m]       = __ushort_as_bfloat16((unsigned short)(l2 & 0xffffu));
        kt_lo[(dp + 1) * KLD + m] = __ushort_as_bfloat16((unsigned short)(l2 >> 16));

        *(uint32_t*)&vs[m * VLD + dp] =
            *(const uint32_t*)&vh[base + (size_t)m * DMODEL + dp];
    }
    for (int m = tid; m < NSEQ; m += 256) {
        *(uint32_t*)&vs[m * VLD + 16] = packh2(1.0f, 0.0f);
        *(uint32_t*)&vs[m * VLD + 18] = 0u;
        *(uint32_t*)&vs[m * VLD + 20] = 0u;
        *(uint32_t*)&vs[m * VLD + 22] = 0u;
    }
    __syncthreads();

    const int lq = lane >> 2;
    const int lc = lane & 3;

    for (int t0 = 0; t0 < NSEQ; t0 += 32) {
        // ---- Q fragments: raw u32 loads (pre-scaled, pre-split)
        uint32_t qh[4], ql[4];
        {
            const size_t qb = base + (size_t)(t0 + wm * 16 + lq) * DMODEL + 2 * lc;
            qh[0] = *(const uint32_t*)&qhi[qb];
            qh[1] = *(const uint32_t*)&qhi[qb + 8 * DMODEL];
            qh[2] = *(const uint32_t*)&qhi[qb + 8];
            qh[3] = *(const uint32_t*)&qhi[qb + 8 * DMODEL + 8];
            ql[0] = *(const uint32_t*)&qlo[qb];
            ql[1] = *(const uint32_t*)&qlo[qb + 8 * DMODEL];
            ql[2] = *(const uint32_t*)&qlo[qb + 8];
            ql[3] = *(const uint32_t*)&qlo[qb + 8 * DMODEL + 8];
        }

        // ---- S = Q K^T (3-term), zero-C first term
        float sacc[16][4];
#pragma unroll
        for (int np = 0; np < 8; np++) {
            const int key0 = wn * 128 + np * 16;
            const uint32_t kaddr =
                sb + OFF_KT_HI + ((lane & 15) * KLD + key0 + (lane >> 4) * 8) * 2;
            uint32_t bh[4], bl[4];
            ldsm_x4t(bh, kaddr);
            ldsm_x4t(bl, kaddr + KT_BYTES);
#pragma unroll
            for (int sub = 0; sub < 2; sub++) {
                const int nt = np * 2 + sub;
                mma_bf16_z(sacc[nt], qh, bh[2 * sub], bh[2 * sub + 1]);
                mma_bf16(sacc[nt], qh, bl[2 * sub], bl[2 * sub + 1]);
                mma_bf16(sacc[nt], ql, bh[2 * sub], bh[2 * sub + 1]);
            }
        }

        // ---- local max, publish, global max
        float m0 = -1e30f, m1 = -1e30f;
#pragma unroll
        for (int nt = 0; nt < 16; nt++) {
            m0 = fmaxf(m0, fmaxf(sacc[nt][0], sacc[nt][1]));
            m1 = fmaxf(m1, fmaxf(sacc[nt][2], sacc[nt][3]));
        }
        m0 = fmaxf(m0, __shfl_xor_sync(0xffffffffu, m0, 1));
        m0 = fmaxf(m0, __shfl_xor_sync(0xffffffffu, m0, 2));
        m1 = fmaxf(m1, __shfl_xor_sync(0xffffffffu, m1, 1));
        m1 = fmaxf(m1, __shfl_xor_sync(0xffffffffu, m1, 2));
        if (lc == 0) {
            maxbuf[wn * 32 + wm * 16 + lq]     = m0;
            maxbuf[wn * 32 + wm * 16 + lq + 8] = m1;
        }
        __syncthreads();

        float M0 = maxbuf[wm * 16 + lq],      M1 = maxbuf[wm * 16 + lq + 8];
#pragma unroll
        for (int w = 1; w < 4; w++) {
            M0 = fmaxf(M0, maxbuf[w * 32 + wm * 16 + lq]);
            M1 = fmaxf(M1, maxbuf[w * 32 + wm * 16 + lq + 8]);
        }

        // ---- P = exp2(s - M) packed to fp16
        uint32_t ph_all[32];
#pragma unroll
        for (int nt = 0; nt < 16; nt++) {
            const float e0 = exp2f(sacc[nt][0] - M0);
            const float e1 = exp2f(sacc[nt][1] - M0);
            const float e2 = exp2f(sacc[nt][2] - M1);
            const float e3 = exp2f(sacc[nt][3] - M1);
            ph_all[nt * 2]     = packh2(e0, e1);
            ph_all[nt * 2 + 1] = packh2(e2, e3);
        }

        // ---- O_num = P V ; row weights via ones-column mma
        float oac[2][4], ow[4];
#pragma unroll
        for (int t = 0; t < 8; t++) {
            const uint32_t* ph = &ph_all[4 * t];
            const int key0 = wn * 128 + t * 16;
            const uint32_t vaddr =
                sb + OFF_VS + ((key0 + (lane & 15)) * VLD + (lane >> 4) * 8) * 2;
            uint32_t vhf[4], vo1[2];
            ldsm_x4t(vhf, vaddr);
            ldsm_x2t(vo1, sb + OFF_VS + ((key0 + (lane & 15)) * VLD + 16) * 2);
            if (t == 0) {
                mma_f16_z(oac[0], ph, vhf[0], vhf[1]);
                mma_f16_z(oac[1], ph, vhf[2], vhf[3]);
                mma_f16_z(ow,     ph, vo1[0], vo1[1]);
            } else {
                mma_f16(oac[0], ph, vhf[0], vhf[1]);
                mma_f16(oac[1], ph, vhf[2], vhf[3]);
                mma_f16(ow,     ph, vo1[0], vo1[1]);
            }
        }

        // ---- publish partials, reduce, normalize, store split O
        {
            float* ob = obuf + wn * 512;
            const int r0 = wm * 16 + lq;
#pragma unroll
            for (int sub = 0; sub < 2; sub++) {
                const int d0 = sub * 8 + 2 * lc;
                *(float2*)&ob[r0 * 16 + d0] =
                    make_float2(oac[sub][0], oac[sub][1]);
                *(float2*)&ob[(r0 + 8) * 16 + d0] =
                    make_float2(oac[sub][2], oac[sub][3]);
            }
            if (lc == 0) {
                wgtbuf[wn * 32 + r0]     = ow[0];
                wgtbuf[wn * 32 + r0 + 8] = ow[2];
            }
        }
        __syncthreads();
        if (tid < 128) {
            const int q4  = tid * 4;
            const int row = q4 >> 4;
            const int d0  = q4 & 15;
            const float4 a = *(const float4*)&obuf[row * 16 + d0];
            const float4 b = *(const float4*)&obuf[512 + row * 16 + d0];
            const float4 c = *(const float4*)&obuf[1024 + row * 16 + d0];
            const float4 d = *(const float4*)&obuf[1536 + row * 16 + d0];
            const float wsum = wgtbuf[row] + wgtbuf[32 + row]
                             + wgtbuf[64 + row] + wgtbuf[96 + row];
            const float inv = 1.0f / wsum;
            float4 r;
            r.x = (a.x + b.x + c.x + d.x) * inv;
            r.y = (a.y + b.y + c.y + d.y) * inv;
            r.z = (a.z + b.z + c.z + d.z) * inv;
            r.w = (a.w + b.w + c.w + d.w) * inv;
            uint32_t h0, l0, h1, l1;
            split2(r.x, r.y, h0, l0);
            split2(r.z, r.w, h1, l1);
            const size_t go = base + (size_t)(t0 + row) * DMODEL + d0;
            *(uint2*)&ohi[go] = make_uint2(h0, h1);
            *(uint2*)&olo[go] = make_uint2(l0, l1);
        }
        __syncthreads();
    }
}

// ===========================================================================
extern "C" void kernel_launch(void* const* d_in, const int* in_sizes, int n_in,
                              void* d_out, int out_size)
{
    const float* X   = (const float*)d_in[0];
    const float* STE = (const float*)d_in[1];
    const float* Wq  = (const float*)d_in[2];
    const float* bq  = (const float*)d_in[3];
    const float* Wk  = (const float*)d_in[4];
    const float* bk  = (const float*)d_in[5];
    const float* Wv  = (const float*)d_in[6];
    const float* bv  = (const float*)d_in[7];
    const float* Wo  = (const float*)d_in[8];
    const float* bo  = (const float*)d_in[9];
    float* out = (float*)d_out;

    const int M  = in_sizes[0] / DMODEL;   // 49152
    const int BT = M / NSEQ;               // 96

    __nv_bfloat16 *qhi, *qlo, *khi, *klo, *ahi, *alo, *whi, *wlo, *ohi, *olo;
    __half *vh;
    cudaGetSymbolAddress((void**)&qhi, g_qhi);
    cudaGetSymbolAddress((void**)&qlo, g_qlo);
    cudaGetSymbolAddress((void**)&khi, g_khi);
    cudaGetSymbolAddress((void**)&klo, g_klo);
    cudaGetSymbolAddress((void**)&vh,  g_vh);
    cudaGetSymbolAddress((void**)&ahi, g_ahi);
    cudaGetSymbolAddress((void**)&alo, g_alo);
    cudaGetSymbolAddress((void**)&whi, g_whi);
    cudaGetSymbolAddress((void**)&wlo, g_wlo);
    cudaGetSymbolAddress((void**)&ohi, g_ohi);
    cudaGetSymbolAddress((void**)&olo, g_olo);

    presplit_x_kernel<<<4608, 256>>>(X, STE, M, ahi, alo);
    presplit_w_kernel<<<160, 256>>>(Wq, Wk, Wv, Wo, whi, wlo);

    cudaFuncSetAttribute(qkv_grid_kernel, cudaFuncAttributeMaxDynamicSharedMemorySize,
                         GEMM_SMEM);
    qkv_grid_kernel<<<dim3(3, M / 128), 256, GEMM_SMEM>>>(
        ahi, alo, whi, wlo, bq, bk, bv, qhi, qlo, khi, klo, vh);

    cudaFuncSetAttribute(attn_tc_kernel, cudaFuncAttributeMaxDynamicSharedMemorySize,
                         ATTN_SMEM);
    attn_tc_kernel<<<dim3(BT, KHEADS), 256, ATTN_SMEM>>>(
        qhi, qlo, khi, klo, vh, ohi, olo);

    cudaFuncSetAttribute(gemm_ps_kernel, cudaFuncAttributeMaxDynamicSharedMemorySize,
                         GEMM_SMEM);
    gemm_ps_kernel<<<M / 128, 256, GEMM_SMEM>>>(ohi, olo, 128, 128,
                                                whi + WOFF_O, wlo + WOFF_O, bo, out);
}

// round 17
// speedup vs baseline: 1.4577x; 1.0065x over previous
#include <cuda_runtime.h>
#include <cuda_bf16.h>
#include <cuda_fp16.h>
#include <cstdint>

// Problem constants: B=8, T=12, N=512, D_MODEL=128, K_HEADS=8, D_HEAD=16.
#define DMODEL   128
#define KHEADS   8
#define DHEAD    16
#define NSEQ     512
#define MMAX     49152

// ---------------- generic-ISA tensor helpers (compute_103-safe) ------------
__device__ __forceinline__ uint32_t smem_to_u32(const void* p) {
    uint32_t a;
    asm("{ .reg .u64 t; cvta.to.shared.u64 t, %1; cvt.u32.u64 %0, t; }"
        : "=r"(a) : "l"(p));
    return a;
}
__device__ __forceinline__ void ldsm_x4(uint32_t* r, uint32_t addr) {
    asm volatile("ldmatrix.sync.aligned.m8n8.x4.shared.b16 {%0,%1,%2,%3}, [%4];"
                 : "=r"(r[0]), "=r"(r[1]), "=r"(r[2]), "=r"(r[3]) : "r"(addr));
}
__device__ __forceinline__ void ldsm_x4t(uint32_t* r, uint32_t addr) {
    asm volatile("ldmatrix.sync.aligned.m8n8.x4.trans.shared.b16 {%0,%1,%2,%3}, [%4];"
                 : "=r"(r[0]), "=r"(r[1]), "=r"(r[2]), "=r"(r[3]) : "r"(addr));
}
__device__ __forceinline__ void mma_bf16(float* d, const uint32_t* a,
                                         uint32_t b0, uint32_t b1) {
    asm volatile("mma.sync.aligned.m16n8k16.row.col.f32.bf16.bf16.f32 "
                 "{%0,%1,%2,%3}, {%4,%5,%6,%7}, {%8,%9}, {%0,%1,%2,%3};"
                 : "+f"(d[0]), "+f"(d[1]), "+f"(d[2]), "+f"(d[3])
                 : "r"(a[0]), "r"(a[1]), "r"(a[2]), "r"(a[3]), "r"(b0), "r"(b1));
}
__device__ __forceinline__ void mma_bf16_z(float* d, const uint32_t* a,
                                           uint32_t b0, uint32_t b1) {
    asm volatile("mma.sync.aligned.m16n8k16.row.col.f32.bf16.bf16.f32 "
                 "{%0,%1,%2,%3}, {%4,%5,%6,%7}, {%8,%9}, {%10,%10,%10,%10};"
                 : "=f"(d[0]), "=f"(d[1]), "=f"(d[2]), "=f"(d[3])
                 : "r"(a[0]), "r"(a[1]), "r"(a[2]), "r"(a[3]), "r"(b0), "r"(b1),
                   "f"(0.0f));
}
__device__ __forceinline__ void mma_f16(float* d, const uint32_t* a,
                                        uint32_t b0, uint32_t b1) {
    asm volatile("mma.sync.aligned.m16n8k16.row.col.f32.f16.f16.f32 "
                 "{%0,%1,%2,%3}, {%4,%5,%6,%7}, {%8,%9}, {%0,%1,%2,%3};"
                 : "+f"(d[0]), "+f"(d[1]), "+f"(d[2]), "+f"(d[3])
                 : "r"(a[0]), "r"(a[1]), "r"(a[2]), "r"(a[3]), "r"(b0), "r"(b1));
}
__device__ __forceinline__ void mma_f16_z(float* d, const uint32_t* a,
                                          uint32_t b0, uint32_t b1) {
    asm volatile("mma.sync.aligned.m16n8k16.row.col.f32.f16.f16.f32 "
                 "{%0,%1,%2,%3}, {%4,%5,%6,%7}, {%8,%9}, {%10,%10,%10,%10};"
                 : "=f"(d[0]), "=f"(d[1]), "=f"(d[2]), "=f"(d[3])
                 : "r"(a[0]), "r"(a[1]), "r"(a[2]), "r"(a[3]), "r"(b0), "r"(b1),
                   "f"(0.0f));
}
#define CP_ASYNC16(dst_u32, src_ptr) \
    asm volatile("cp.async.ca.shared.global [%0], [%1], 16;" \
                 :: "r"(dst_u32), "l"(src_ptr))
#define CP_COMMIT() asm volatile("cp.async.commit_group;" ::: "memory")
#define CP_WAIT(n)  asm volatile("cp.async.wait_group %0;" :: "n"(n) : "memory")

__device__ __forceinline__ void split2(float x, float y, uint32_t& hi, uint32_t& lo) {
    uint32_t h;
    asm("cvt.rn.bf16x2.f32 %0, %1, %2;" : "=r"(h) : "f"(y), "f"(x));
    const float hx = __uint_as_float(h << 16);
    const float hy = __uint_as_float(h & 0xffff0000u);
    uint32_t l;
    asm("cvt.rn.bf16x2.f32 %0, %1, %2;" : "=r"(l) : "f"(y - hy), "f"(x - hx));
    hi = h; lo = l;
}
__device__ __forceinline__ uint32_t packh2(float x, float y) {
    const half2 h = __floats2half2_rn(x, y);
    return *(const uint32_t*)&h;
}

#define QSCALE 0.3606737602f    /* 0.25 * log2(e) */

// ---------------- scratch --------------------------------------------------
__device__ __nv_bfloat16 g_qhi[(size_t)MMAX * DMODEL];
__device__ __nv_bfloat16 g_qlo[(size_t)MMAX * DMODEL];
__device__ __nv_bfloat16 g_khi[(size_t)MMAX * DMODEL];
__device__ __nv_bfloat16 g_klo[(size_t)MMAX * DMODEL];
__device__ __half        g_vh [(size_t)MMAX * DMODEL];
__device__ __nv_bfloat16 g_ahi[(size_t)MMAX * 384];
__device__ __nv_bfloat16 g_alo[(size_t)MMAX * 384];
__device__ __nv_bfloat16 g_ohi[(size_t)MMAX * DMODEL];
__device__ __nv_bfloat16 g_olo[(size_t)MMAX * DMODEL];
#define W_TOTAL (3 * 49152 + 16384)
__device__ __nv_bfloat16 g_whi[W_TOTAL];
__device__ __nv_bfloat16 g_wlo[W_TOTAL];
#define WOFF_O 147456

// ===========================================================================
// Pre-split kernels
// ===========================================================================
__global__ void presplit_x_kernel(const float* __restrict__ X,
                                  const float* __restrict__ STE, int M,
                                  __nv_bfloat16* __restrict__ ahi,
                                  __nv_bfloat16* __restrict__ alo)
{
    const int total = M * 96;
    for (int i = blockIdx.x * blockDim.x + threadIdx.x; i < total;
         i += gridDim.x * blockDim.x) {
        const int m = i / 96, c = (i % 96) * 4;
        const float4 x = (c < 128)
            ? *(const float4*)&X[(size_t)m * 128 + c]
            : *(const float4*)&STE[(size_t)m * 256 + (c - 128)];
        uint32_t h0, l0, h1, l1;
        split2(x.x, x.y, h0, l0);
        split2(x.z, x.w, h1, l1);
        *(uint2*)&ahi[(size_t)m * 384 + c] = make_uint2(h0, h1);
        *(uint2*)&alo[(size_t)m * 384 + c] = make_uint2(l0, l1);
    }
}

__global__ void presplit_w_kernel(const float* __restrict__ Wq,
                                  const float* __restrict__ Wk,
                                  const float* __restrict__ Wv,
                                  const float* __restrict__ Wo,
                                  __nv_bfloat16* __restrict__ whi,
                                  __nv_bfloat16* __restrict__ wlo)
{
    const int i = blockIdx.x * blockDim.x + threadIdx.x;
    if (i >= W_TOTAL / 4) return;
    const float* src; int off;
    if      (i < 12288) { src = Wq; off = 0; }
    else if (i < 24576) { src = Wk; off = 12288; }
    else if (i < 36864) { src = Wv; off = 24576; }
    else                { src = Wo; off = 36864; }
    const int j = (i - off) * 4;
    const float4 x = *(const float4*)&src[j];
    uint32_t h0, l0, h1, l1;
    split2(x.x, x.y, h0, l0);
    split2(x.z, x.w, h1, l1);
    *(uint2*)&whi[off * 4 + j] = make_uint2(h0, h1);
    *(uint2*)&wlo[off * 4 + j] = make_uint2(l0, l1);
}

// ===========================================================================
// Pipelined mma.sync GEMM core, templated epilogue (unchanged from R16):
//   MODE 0: fp32 C   MODE 1: q -> scaled split-bf16
//   MODE 2: k -> split-bf16   MODE 3: v -> fp16
// ===========================================================================
#define GK      32
#define GA_LD   40
#define GB_LD   136
#define GA_BUF  (128 * GA_LD * 2)
#define GB_BUF  (GK * GB_LD * 2)
#define GSM_A   0
#define GSM_B   (4 * GA_BUF)
#define GEMM_SMEM (GSM_B + 4 * GB_BUF)   // 75776

template<int MODE>
__device__ __forceinline__ void gemm_core_t(
    const __nv_bfloat16* __restrict__ Ahi,
    const __nv_bfloat16* __restrict__ Alo,
    int lda, int K, int rowBase,
    const __nv_bfloat16* __restrict__ Whi,
    const __nv_bfloat16* __restrict__ Wlo,
    const float* __restrict__ bias,
    void* __restrict__ D0, void* __restrict__ D1,
    uint32_t sb)
{
    const int tid  = threadIdx.x;
    const int warp = tid >> 5;
    const int lane = tid & 31;
    const int wm   = warp & 3;
    const int wn   = warp >> 2;

    float acc[2][8][4];
#pragma unroll
    for (int mt = 0; mt < 2; mt++)
#pragma unroll
        for (int nt = 0; nt < 8; nt++)
#pragma unroll
            for (int e = 0; e < 4; e++) acc[mt][nt][e] = 0.0f;

    const int nChunks = K / GK;

    auto load_chunk = [&](int c, int buf) {
        const int k0 = c * GK;
        {
            const int r = tid >> 1;
#pragma unroll
            for (int hl = 0; hl < 2; hl++) {
                const __nv_bfloat16* gsrc =
                    (hl ? Alo : Ahi) + (size_t)(rowBase + r) * lda + k0;
                const uint32_t dbase =
                    sb + GSM_A + (buf * 2 + hl) * GA_BUF + r * (GA_LD * 2);
#pragma unroll
                for (int s2 = 0; s2 < 2; s2++) {
                    const int s = (tid & 1) * 2 + s2;
                    CP_ASYNC16(dbase + s * 16, gsrc + s * 8);
                }
            }
        }
        {
            const int kk = tid >> 3;
#pragma unroll
            for (int hl = 0; hl < 2; hl++) {
                const __nv_bfloat16* gsrc =
                    (hl ? Wlo : Whi) + (size_t)(k0 + kk) * 128;
                const uint32_t dbase =
                    sb + GSM_B + (buf * 2 + hl) * GB_BUF + kk * (GB_LD * 2);
#pragma unroll
                for (int s2 = 0; s2 < 2; s2++) {
                    const int s = (tid & 7) * 2 + s2;
                    CP_ASYNC16(dbase + s * 16, gsrc + s * 8);
                }
            }
        }
        CP_COMMIT();
    };

    load_chunk(0, 0);

    for (int c = 0; c < nChunks; c++) {
        if (c + 1 < nChunks) { load_chunk(c + 1, (c + 1) & 1); CP_WAIT(1); }
        else                 { CP_WAIT(0); }
        __syncthreads();

        const int buf = c & 1;
        const uint32_t abase_h = sb + GSM_A + (buf * 2 + 0) * GA_BUF;
        const uint32_t abase_l = sb + GSM_A + (buf * 2 + 1) * GA_BUF;
        const uint32_t bbase_h = sb + GSM_B + (buf * 2 + 0) * GB_BUF;
        const uint32_t bbase_l = sb + GSM_B + (buf * 2 + 1) * GB_BUF;

#pragma unroll
        for (int ks = 0; ks < 2; ks++) {
            uint32_t ah[2][4], al[2][4];
            const int arow = lane & 15;
            const int acol = ks * 16 + (lane >> 4) * 8;
#pragma unroll
            for (int mt = 0; mt < 2; mt++) {
                const uint32_t aoff =
                    ((wm * 32 + mt * 16 + arow) * GA_LD + acol) * 2;
                ldsm_x4(ah[mt], abase_h + aoff);
                ldsm_x4(al[mt], abase_l + aoff);
            }
            const int brow = ks * 16 + (lane & 15);
#pragma unroll
            for (int np = 0; np < 4; np++) {
                const uint32_t boff =
                    (brow * GB_LD + wn * 64 + np * 16 + (lane >> 4) * 8) * 2;
                uint32_t bh[4], bl[4];
                ldsm_x4t(bh, bbase_h + boff);
                ldsm_x4t(bl, bbase_l + boff);
#pragma unroll
                for (int sub = 0; sub < 2; sub++) {
                    const int nt = np * 2 + sub;
#pragma unroll
                    for (int mt = 0; mt < 2; mt++) {
                        mma_bf16(acc[mt][nt], ah[mt], bh[2 * sub], bh[2 * sub + 1]);
                        mma_bf16(acc[mt][nt], ah[mt], bl[2 * sub], bl[2 * sub + 1]);
                        mma_bf16(acc[mt][nt], al[mt], bh[2 * sub], bh[2 * sub + 1]);
                    }
                }
            }
        }
        __syncthreads();
    }

#pragma unroll
    for (int mt = 0; mt < 2; mt++) {
        const int r0 = rowBase + wm * 32 + mt * 16 + (lane >> 2);
#pragma unroll
        for (int nt = 0; nt < 8; nt++) {
            const int cc = wn * 64 + nt * 8 + (lane & 3) * 2;
            const float b0 = bias[cc], b1 = bias[cc + 1];
            const float v00 = fmaxf(acc[mt][nt][0] + b0, 0.0f);
            const float v01 = fmaxf(acc[mt][nt][1] + b1, 0.0f);
            const float v10 = fmaxf(acc[mt][nt][2] + b0, 0.0f);
            const float v11 = fmaxf(acc[mt][nt][3] + b1, 0.0f);
            const size_t o0 = (size_t)r0 * 128 + cc;
            const size_t o1 = (size_t)(r0 + 8) * 128 + cc;
            if (MODE == 0) {
                *(float2*)&((float*)D0)[o0] = make_float2(v00, v01);
                *(float2*)&((float*)D0)[o1] = make_float2(v10, v11);
            } else if (MODE == 1 || MODE == 2) {
                const float s = (MODE == 1) ? QSCALE : 1.0f;
                uint32_t h0, l0, h1, l1;
                split2(s * v00, s * v01, h0, l0);
                split2(s * v10, s * v11, h1, l1);
                *(uint32_t*)&((__nv_bfloat16*)D0)[o0] = h0;
                *(uint32_t*)&((__nv_bfloat16*)D1)[o0] = l0;
                *(uint32_t*)&((__nv_bfloat16*)D0)[o1] = h1;
                *(uint32_t*)&((__nv_bfloat16*)D1)[o1] = l1;
            } else {
                *(uint32_t*)&((__half*)D0)[o0] = packh2(v00, v01);
                *(uint32_t*)&((__half*)D0)[o1] = packh2(v10, v11);
            }
        }
    }
}

__global__ __launch_bounds__(256, 2)
void qkv_grid_kernel(const __nv_bfloat16* __restrict__ Ahi,
                     const __nv_bfloat16* __restrict__ Alo,
                     const __nv_bfloat16* __restrict__ whi,
                     const __nv_bfloat16* __restrict__ wlo,
                     const float* __restrict__ bq,
                     const float* __restrict__ bk,
                     const float* __restrict__ bv,
                     __nv_bfloat16* __restrict__ qhi,
                     __nv_bfloat16* __restrict__ qlo,
                     __nv_bfloat16* __restrict__ khi,
                     __nv_bfloat16* __restrict__ klo,
                     __half* __restrict__ vh)
{
    extern __shared__ __align__(16) char smc[];
    const uint32_t sb = smem_to_u32(smc);
    const int wsel = blockIdx.x;
    const int rowBase = blockIdx.y * 128;
    const __nv_bfloat16* Whi = whi + (size_t)wsel * 49152;
    const __nv_bfloat16* Wlo = wlo + (size_t)wsel * 49152;
    if (wsel == 0)
        gemm_core_t<1>(Ahi, Alo, 384, 384, rowBase, Whi, Wlo, bq, qhi, qlo, sb);
    else if (wsel == 1)
        gemm_core_t<2>(Ahi, Alo, 384, 384, rowBase, Whi, Wlo, bk, khi, klo, sb);
    else
        gemm_core_t<3>(Ahi, Alo, 384, 384, rowBase, Whi, Wlo, bv, vh, nullptr, sb);
}

__global__ __launch_bounds__(256, 2)
void gemm_ps_kernel(const __nv_bfloat16* __restrict__ Ahi,
                    const __nv_bfloat16* __restrict__ Alo,
                    int lda, int K,
                    const __nv_bfloat16* __restrict__ Whi,
                    const __nv_bfloat16* __restrict__ Wlo,
                    const float* __restrict__ bias, float* __restrict__ C)
{
    extern __shared__ __align__(16) char smc[];
    const uint32_t sb = smem_to_u32(smc);
    gemm_core_t<0>(Ahi, Alo, lda, K, blockIdx.x * 128, Whi, Wlo, bias, C,
                   nullptr, sb);
}

// ===========================================================================
// Attention v9: K in natural [key][d] layout (vectorized staging, non-trans
// ldsm, hoisted t0-invariant addresses); ones-column B-fragment is a
// register constant (no ldsm.x2t, no ones staging). Math identical to v8.
// ===========================================================================
#define VLD 24                            // halfs per row: 16 data + 8 pad
#define PLANE_BYTES (NSEQ * VLD * 2)      // 24576
#define OFF_KS_HI 0
#define OFF_KS_LO (OFF_KS_HI + PLANE_BYTES)
#define OFF_VS    (OFF_KS_LO + PLANE_BYTES)
#define OFF_OBUF  (OFF_VS + PLANE_BYTES)
#define OFF_MAX   (OFF_OBUF + 4 * 32 * 16 * 4)
#define OFF_WGT   (OFF_MAX + 4 * 32 * 4)
#define ATTN_SMEM (OFF_WGT + 4 * 32 * 4)  // 82944 bytes

__global__ __launch_bounds__(256, 2)
void attn_tc_kernel(const __nv_bfloat16* __restrict__ qhi,
                    const __nv_bfloat16* __restrict__ qlo,
                    const __nv_bfloat16* __restrict__ khi,
                    const __nv_bfloat16* __restrict__ klo,
                    const __half* __restrict__ vh,
                    __nv_bfloat16* __restrict__ ohi,
                    __nv_bfloat16* __restrict__ olo)
{
    extern __shared__ __align__(16) char smc[];
    const uint32_t sb = smem_to_u32(smc);
    __half* ks_hi = (__half*)(smc + OFF_KS_HI);   // raw 16-bit storage
    __half* ks_lo = (__half*)(smc + OFF_KS_LO);
    __half* vs    = (__half*)(smc + OFF_VS);
    float*  obuf   = (float*)(smc + OFF_OBUF);
    float*  maxbuf = (float*)(smc + OFF_MAX);
    float*  wgtbuf = (float*)(smc + OFF_WGT);

    const int bt   = blockIdx.x;
    const int h    = blockIdx.y;
    const int tid  = threadIdx.x;
    const int warp = tid >> 5;
    const int lane = tid & 31;
    const int wm   = warp & 1;
    const int wn   = warp >> 1;
    const size_t base = (size_t)bt * NSEQ * DMODEL + h * DHEAD;

    // ---- stage K hi/lo and V: pure uint4 copies, natural [key][d] layout
    for (int i = tid; i < NSEQ * 2; i += 256) {
        const int m = i >> 1, seg = (i & 1) * 8;
        const size_t g = base + (size_t)m * DMODEL + seg;
        const int s = m * VLD + seg;
        *(uint4*)&ks_hi[s] = *(const uint4*)&khi[g];
        *(uint4*)&ks_lo[s] = *(const uint4*)&klo[g];
        *(uint4*)&vs[s]    = *(const uint4*)&vh[g];
    }
    __syncthreads();

    const int lq = lane >> 2;
    const int lc = lane & 3;

    // ---- t0-invariant ldsm base addresses
    // K (non-trans x4): rows = keys, col = d-half
    const int krow = (lane & 7) + ((lane >> 4) << 3);
    const int kcol = ((lane >> 3) & 1) * 8;
    const uint32_t kb_hi = sb + OFF_KS_HI +
        (uint32_t)((krow * VLD + kcol) * 2) + (uint32_t)(wn * (128 * VLD * 2));
    const uint32_t kb_lo = kb_hi + PLANE_BYTES;
    // V (trans x4): rows = keys, col = d-half
    const uint32_t vb = sb + OFF_VS +
        (uint32_t)((((lane & 15) * VLD) + ((lane >> 4) << 3)) * 2) +
        (uint32_t)(wn * (128 * VLD * 2));
    // ones-column B fragment (n = lane>>2 == 0 holds 1.0 in both halves)
    const uint32_t vone = (lane < 4) ? 0x3C003C00u : 0u;

    for (int t0 = 0; t0 < NSEQ; t0 += 32) {
        // ---- Q fragments: raw u32 loads (pre-scaled, pre-split)
        uint32_t qh[4], ql[4];
        {
            const size_t qb = base + (size_t)(t0 + wm * 16 + lq) * DMODEL + 2 * lc;
            qh[0] = *(const uint32_t*)&qhi[qb];
            qh[1] = *(const uint32_t*)&qhi[qb + 8 * DMODEL];
            qh[2] = *(const uint32_t*)&qhi[qb + 8];
            qh[3] = *(const uint32_t*)&qhi[qb + 8 * DMODEL + 8];
            ql[0] = *(const uint32_t*)&qlo[qb];
            ql[1] = *(const uint32_t*)&qlo[qb + 8 * DMODEL];
            ql[2] = *(const uint32_t*)&qlo[qb + 8];
            ql[3] = *(const uint32_t*)&qlo[qb + 8 * DMODEL + 8];
        }

        // ---- S = Q K^T (3-term), zero-C first term
        float sacc[16][4];
#pragma unroll
        for (int np = 0; np < 8; np++) {
            uint32_t bh[4], bl[4];
            ldsm_x4(bh, kb_hi + np * (16 * VLD * 2));
            ldsm_x4(bl, kb_lo + np * (16 * VLD * 2));
#pragma unroll
            for (int sub = 0; sub < 2; sub++) {
                const int nt = np * 2 + sub;
                mma_bf16_z(sacc[nt], qh, bh[2 * sub], bh[2 * sub + 1]);
                mma_bf16(sacc[nt], qh, bl[2 * sub], bl[2 * sub + 1]);
                mma_bf16(sacc[nt], ql, bh[2 * sub], bh[2 * sub + 1]);
            }
        }

        // ---- local max, publish, global max
        float m0 = -1e30f, m1 = -1e30f;
#pragma unroll
        for (int nt = 0; nt < 16; nt++) {
            m0 = fmaxf(m0, fmaxf(sacc[nt][0], sacc[nt][1]));
            m1 = fmaxf(m1, fmaxf(sacc[nt][2], sacc[nt][3]));
        }
        m0 = fmaxf(m0, __shfl_xor_sync(0xffffffffu, m0, 1));
        m0 = fmaxf(m0, __shfl_xor_sync(0xffffffffu, m0, 2));
        m1 = fmaxf(m1, __shfl_xor_sync(0xffffffffu, m1, 1));
        m1 = fmaxf(m1, __shfl_xor_sync(0xffffffffu, m1, 2));
        if (lc == 0) {
            maxbuf[wn * 32 + wm * 16 + lq]     = m0;
            maxbuf[wn * 32 + wm * 16 + lq + 8] = m1;
        }
        __syncthreads();

        float M0 = maxbuf[wm * 16 + lq],      M1 = maxbuf[wm * 16 + lq + 8];
#pragma unroll
        for (int w = 1; w < 4; w++) {
            M0 = fmaxf(M0, maxbuf[w * 32 + wm * 16 + lq]);
            M1 = fmaxf(M1, maxbuf[w * 32 + wm * 16 + lq + 8]);
        }

        // ---- P = exp2(s - M) packed to fp16
        uint32_t ph_all[32];
#pragma unroll
        for (int nt = 0; nt < 16; nt++) {
            const float e0 = exp2f(sacc[nt][0] - M0);
            const float e1 = exp2f(sacc[nt][1] - M0);
            const float e2 = exp2f(sacc[nt][2] - M1);
            const float e3 = exp2f(sacc[nt][3] - M1);
            ph_all[nt * 2]     = packh2(e0, e1);
            ph_all[nt * 2 + 1] = packh2(e2, e3);
        }

        // ---- O_num = P V ; row weights via constant ones-fragment mma
        float oac[2][4], ow[4];
#pragma unroll
        for (int t = 0; t < 8; t++) {
            const uint32_t* ph = &ph_all[4 * t];
            uint32_t vhf[4];
            ldsm_x4t(vhf, vb + t * (16 * VLD * 2));
            if (t == 0) {
                mma_f16_z(oac[0], ph, vhf[0], vhf[1]);
                mma_f16_z(oac[1], ph, vhf[2], vhf[3]);
                mma_f16_z(ow,     ph, vone, vone);
            } else {
                mma_f16(oac[0], ph, vhf[0], vhf[1]);
                mma_f16(oac[1], ph, vhf[2], vhf[3]);
                mma_f16(ow,     ph, vone, vone);
            }
        }

        // ---- publish partials, reduce, normalize, store split O
        {
            float* ob = obuf + wn * 512;
            const int r0 = wm * 16 + lq;
#pragma unroll
            for (int sub = 0; sub < 2; sub++) {
                const int d0 = sub * 8 + 2 * lc;
                *(float2*)&ob[r0 * 16 + d0] =
                    make_float2(oac[sub][0], oac[sub][1]);
                *(float2*)&ob[(r0 + 8) * 16 + d0] =
                    make_float2(oac[sub][2], oac[sub][3]);
            }
            if (lc == 0) {
                wgtbuf[wn * 32 + r0]     = ow[0];
                wgtbuf[wn * 32 + r0 + 8] = ow[2];
            }
        }
        __syncthreads();
        if (tid < 128) {
            const int q4  = tid * 4;
            const int row = q4 >> 4;
            const int d0  = q4 & 15;
            const float4 a = *(const float4*)&obuf[row * 16 + d0];
            const float4 b = *(const float4*)&obuf[512 + row * 16 + d0];
            const float4 c = *(const float4*)&obuf[1024 + row * 16 + d0];
            const float4 d = *(const float4*)&obuf[1536 + row * 16 + d0];
            const float wsum = wgtbuf[row] + wgtbuf[32 + row]
                             + wgtbuf[64 + row] + wgtbuf[96 + row];
            const float inv = 1.0f / wsum;
            float4 r;
            r.x = (a.x + b.x + c.x + d.x) * inv;
            r.y = (a.y + b.y + c.y + d.y) * inv;
            r.z = (a.z + b.z + c.z + d.z) * inv;
            r.w = (a.w + b.w + c.w + d.w) * inv;
            uint32_t h0, l0, h1, l1;
            split2(r.x, r.y, h0, l0);
            split2(r.z, r.w, h1, l1);
            const size_t go = base + (size_t)(t0 + row) * DMODEL + d0;
            *(uint2*)&ohi[go] = make_uint2(h0, h1);
            *(uint2*)&olo[go] = make_uint2(l0, l1);
        }
        __syncthreads();
    }
}

// ===========================================================================
extern "C" void kernel_launch(void* const* d_in, const int* in_sizes, int n_in,
                              void* d_out, int out_size)
{
    const float* X   = (const float*)d_in[0];
    const float* STE = (const float*)d_in[1];
    const float* Wq  = (const float*)d_in[2];
    const float* bq  = (const float*)d_in[3];
    const float* Wk  = (const float*)d_in[4];
    const float* bk  = (const float*)d_in[5];
    const float* Wv  = (const float*)d_in[6];
    const float* bv  = (const float*)d_in[7];
    const float* Wo  = (const float*)d_in[8];
    const float* bo  = (const float*)d_in[9];
    float* out = (float*)d_out;

    const int M  = in_sizes[0] / DMODEL;   // 49152
    const int BT = M / NSEQ;               // 96

    __nv_bfloat16 *qhi, *qlo, *khi, *klo, *ahi, *alo, *whi, *wlo, *ohi, *olo;
    __half *vh;
    cudaGetSymbolAddress((void**)&qhi, g_qhi);
    cudaGetSymbolAddress((void**)&qlo, g_qlo);
    cudaGetSymbolAddress((void**)&khi, g_khi);
    cudaGetSymbolAddress((void**)&klo, g_klo);
    cudaGetSymbolAddress((void**)&vh,  g_vh);
    cudaGetSymbolAddress((void**)&ahi, g_ahi);
    cudaGetSymbolAddress((void**)&alo, g_alo);
    cudaGetSymbolAddress((void**)&whi, g_whi);
    cudaGetSymbolAddress((void**)&wlo, g_wlo);
    cudaGetSymbolAddress((void**)&ohi, g_ohi);
    cudaGetSymbolAddress((void**)&olo, g_olo);

    presplit_x_kernel<<<4608, 256>>>(X, STE, M, ahi, alo);
    presplit_w_kernel<<<160, 256>>>(Wq, Wk, Wv, Wo, whi, wlo);

    cudaFuncSetAttribute(qkv_grid_kernel, cudaFuncAttributeMaxDynamicSharedMemorySize,
                         GEMM_SMEM);
    qkv_grid_kernel<<<dim3(3, M / 128), 256, GEMM_SMEM>>>(
        ahi, alo, whi, wlo, bq, bk, bv, qhi, qlo, khi, klo, vh);

    cudaFuncSetAttribute(attn_tc_kernel, cudaFuncAttributeMaxDynamicSharedMemorySize,
                         ATTN_SMEM);
    attn_tc_kernel<<<dim3(BT, KHEADS), 256, ATTN_SMEM>>>(
        qhi, qlo, khi, klo, vh, ohi, olo);

    cudaFuncSetAttribute(gemm_ps_kernel, cudaFuncAttributeMaxDynamicSharedMemorySize,
                         GEMM_SMEM);
    gemm_ps_kernel<<<M / 128, 256, GEMM_SMEM>>>(ohi, olo, 128, 128,
                                                whi + WOFF_O, wlo + WOFF_O, bo, out);
}